// round 1
// baseline (speedup 1.0000x reference)
#include <cuda_runtime.h>
#include <cuda_bf16.h>

// ---------------- problem constants ----------------
#define BATCH 4
#define CH    256
#define HH    48
#define WW    48
#define LL    2304          // HH*WW
#define HEADS 8
#define HD    32
#define INNER 256           // HEADS*HD
#define SCALE 0.17677669529663687f   // 1/sqrt(32)

// ---------------- scratch (static device allocations; no cudaMalloc) ------
__device__ float g_xn[BATCH * LL * CH];          // normalized x,   [b][l][c]
__device__ float g_cn[BATCH * LL * CH];          // normalized ctx, [b][l][c]
__device__ float g_q [BATCH * HEADS * LL * HD];  // [b][h][l][d]
__device__ float g_k [BATCH * HEADS * LL * HD];
__device__ float g_v [BATCH * HEADS * LL * HD];
__device__ float g_ao[BATCH * LL * INNER];       // attention out, [b][l][o]

// ============================================================
// LayerNorm over channels: src [b][c][l]  ->  dst [b][l][c]
// one block per (b,l) position, 256 threads (one per channel)
// ============================================================
__global__ void ln_kernel(const float* __restrict__ src,
                          const float* __restrict__ w,
                          const float* __restrict__ bia,
                          float* __restrict__ dst) {
    int p = blockIdx.x;            // 0..BATCH*LL-1
    int b = p / LL, l = p % LL;
    int c = threadIdx.x;           // 256 threads

    float v = src[(b * CH + c) * LL + l];

    __shared__ float s1[8], s2[8];
    float a = v, q = v * v;
    #pragma unroll
    for (int o = 16; o > 0; o >>= 1) {
        a += __shfl_xor_sync(0xFFFFFFFFu, a, o);
        q += __shfl_xor_sync(0xFFFFFFFFu, q, o);
    }
    if ((c & 31) == 0) { s1[c >> 5] = a; s2[c >> 5] = q; }
    __syncthreads();
    float suma = 0.f, sumq = 0.f;
    #pragma unroll
    for (int i = 0; i < 8; i++) { suma += s1[i]; sumq += s2[i]; }

    float mu  = suma * (1.0f / 256.0f);
    float var = sumq * (1.0f / 256.0f) - mu * mu;
    float inv = rsqrtf(var + 1e-6f);

    dst[p * CH + c] = (v - mu) * inv * w[c] + bia[c];
}

// ============================================================
// QKV projection GEMM:
//   A  : [BATCH*LL][256]  (g_xn or g_cn, k = channel)
//   W  : [256][256]       (row o, contiguous over c)
//   out: [b][h][l][d] with o = h*32+d
// tile 64 rows (positions, by ty) x 64 cols (outputs, by tx)
// ============================================================
__global__ void proj_qkv_kernel(const float* __restrict__ A,
                                const float* __restrict__ W,
                                const float* __restrict__ bias,
                                float* __restrict__ out) {
    __shared__ float As[64][17];
    __shared__ float Ws[64][17];

    int m0 = blockIdx.x * 64;     // position tile
    int n0 = blockIdx.y * 64;     // output tile
    int tid = threadIdx.x;        // 256
    int tx = tid & 15, ty = tid >> 4;

    float acc[4][4];
    #pragma unroll
    for (int i = 0; i < 4; i++)
        #pragma unroll
        for (int j = 0; j < 4; j++) acc[i][j] = 0.f;

    int lr  = tid >> 2;           // 0..63 (load row)
    int lc4 = (tid & 3) * 4;      // 0,4,8,12

    for (int k0 = 0; k0 < 256; k0 += 16) {
        float4 va = *(const float4*)&A[(m0 + lr) * 256 + k0 + lc4];
        As[lr][lc4 + 0] = va.x; As[lr][lc4 + 1] = va.y;
        As[lr][lc4 + 2] = va.z; As[lr][lc4 + 3] = va.w;
        float4 vw = *(const float4*)&W[(n0 + lr) * 256 + k0 + lc4];
        Ws[lr][lc4 + 0] = vw.x; Ws[lr][lc4 + 1] = vw.y;
        Ws[lr][lc4 + 2] = vw.z; Ws[lr][lc4 + 3] = vw.w;
        __syncthreads();

        #pragma unroll
        for (int kk = 0; kk < 16; kk++) {
            float af[4], wf[4];
            #pragma unroll
            for (int i = 0; i < 4; i++) af[i] = As[ty * 4 + i][kk];
            #pragma unroll
            for (int j = 0; j < 4; j++) wf[j] = Ws[tx * 4 + j][kk];
            #pragma unroll
            for (int i = 0; i < 4; i++)
                #pragma unroll
                for (int j = 0; j < 4; j++) acc[i][j] += af[i] * wf[j];
        }
        __syncthreads();
    }

    int o0 = n0 + tx * 4;
    int h  = o0 >> 5, d0 = o0 & 31;
    #pragma unroll
    for (int i = 0; i < 4; i++) {
        int m = m0 + ty * 4 + i;
        int b = m / LL, l = m % LL;
        float4 r;
        r.x = acc[i][0] + bias[o0 + 0];
        r.y = acc[i][1] + bias[o0 + 1];
        r.z = acc[i][2] + bias[o0 + 2];
        r.w = acc[i][3] + bias[o0 + 3];
        *(float4*)&out[(((b * HEADS + h) * LL) + l) * HD + d0] = r;
    }
}

// ============================================================
// Flash attention with relative-position bias.
// grid (18, HEADS, BATCH), 128 threads; thread t owns query q0+t.
// K/V tiles (32 x 32) staged in smem; compacted 95x95 bias table in smem.
// ============================================================
__global__ void __launch_bounds__(128)
attn_kernel(const float* __restrict__ q,
            const float* __restrict__ k,
            const float* __restrict__ v,
            const float* __restrict__ rel_table,
            float* __restrict__ ao) {
    __shared__ float sb[95 * 95];     // bias table for this head (36.1 KB)
    __shared__ float ks[32][32];
    __shared__ float vs[32][32];

    int b = blockIdx.z, h = blockIdx.y;
    int q0 = blockIdx.x * 128;
    int t = threadIdx.x;

    // compact bias table: sb[(dy+47)*95 + (dx+47)], dy,dx in [-47,47]
    for (int i = t; i < 95 * 95; i += 128) {
        int dyi = i / 95, dxi = i % 95;
        int idx = (dyi + 16) * 127 + (dxi + 16);   // (+63-47)=16 offset shift
        sb[i] = rel_table[idx * HEADS + h];
    }

    int qi = q0 + t;
    int yi = qi / WW, xi = qi % WW;

    const float* qp = &q[(((b * HEADS + h) * LL) + qi) * HD];
    float qr[32];
    #pragma unroll
    for (int i = 0; i < 8; i++) {
        float4 f = *(const float4*)&qp[i * 4];
        qr[i * 4 + 0] = f.x * SCALE; qr[i * 4 + 1] = f.y * SCALE;
        qr[i * 4 + 2] = f.z * SCALE; qr[i * 4 + 3] = f.w * SCALE;
    }

    float o[32];
    #pragma unroll
    for (int d = 0; d < 32; d++) o[d] = 0.f;
    float m = -1e30f, lsum = 0.f;

    const float* kb = &k[((b * HEADS + h) * LL) * HD];
    const float* vb = &v[((b * HEADS + h) * LL) * HD];

    for (int j0 = 0; j0 < LL; j0 += 32) {
        // stage K/V tile (coalesced float4 loads)
        for (int i = t; i < 256; i += 128) {
            int row = i >> 3, c4 = (i & 7) << 2;
            *(float4*)&ks[row][c4] = *(const float4*)&kb[(j0 + row) * HD + c4];
            *(float4*)&vs[row][c4] = *(const float4*)&vb[(j0 + row) * HD + c4];
        }
        __syncthreads();

        float s[32];
        int yj = j0 / WW, xj = j0 % WW;
        float mt = -1e30f;
        #pragma unroll
        for (int j = 0; j < 32; j++) {
            float acc = 0.f;
            #pragma unroll
            for (int d4 = 0; d4 < 8; d4++) {
                float4 kv = *(const float4*)&ks[j][d4 * 4];
                acc += qr[d4 * 4 + 0] * kv.x + qr[d4 * 4 + 1] * kv.y
                     + qr[d4 * 4 + 2] * kv.z + qr[d4 * 4 + 3] * kv.w;
            }
            acc += sb[(yi - yj + 47) * 95 + (xi - xj + 47)];
            s[j] = acc;
            mt = fmaxf(mt, acc);
            xj++; if (xj == WW) { xj = 0; yj++; }
        }

        float newm = fmaxf(m, mt);
        float corr = __expf(m - newm);
        lsum *= corr;
        #pragma unroll
        for (int d = 0; d < 32; d++) o[d] *= corr;

        #pragma unroll
        for (int j = 0; j < 32; j++) {
            float p = __expf(s[j] - newm);
            lsum += p;
            #pragma unroll
            for (int d4 = 0; d4 < 8; d4++) {
                float4 vv = *(const float4*)&vs[j][d4 * 4];
                o[d4 * 4 + 0] += p * vv.x; o[d4 * 4 + 1] += p * vv.y;
                o[d4 * 4 + 2] += p * vv.z; o[d4 * 4 + 3] += p * vv.w;
            }
        }
        m = newm;
        __syncthreads();
    }

    float inv = 1.0f / lsum;
    float* op = &ao[(b * LL + qi) * INNER + h * HD];
    #pragma unroll
    for (int d4 = 0; d4 < 8; d4++) {
        float4 r;
        r.x = o[d4 * 4 + 0] * inv; r.y = o[d4 * 4 + 1] * inv;
        r.z = o[d4 * 4 + 2] * inv; r.w = o[d4 * 4 + 3] * inv;
        *(float4*)&op[d4 * 4] = r;
    }
}

// ============================================================
// Output projection + residual:
//   out[b][c][l] = x[b][c][l] + bp[c] + sum_o Wp[c][o] * ao[b][l][o]
// tile 64 rows (l, by tx -> coalesced l-contiguous writes) x 64 cols (c, by ty)
// ============================================================
__global__ void proj_out_kernel(const float* __restrict__ Aao,
                                const float* __restrict__ Wp,
                                const float* __restrict__ bp,
                                const float* __restrict__ x,
                                float* __restrict__ out) {
    __shared__ float As[64][17];
    __shared__ float Ws[64][17];

    int m0 = blockIdx.x * 64;     // position (l) tile
    int n0 = blockIdx.y * 64;     // channel tile
    int tid = threadIdx.x;
    int tx = tid & 15, ty = tid >> 4;

    float acc[4][4];
    #pragma unroll
    for (int i = 0; i < 4; i++)
        #pragma unroll
        for (int j = 0; j < 4; j++) acc[i][j] = 0.f;

    int lr  = tid >> 2;
    int lc4 = (tid & 3) * 4;

    for (int k0 = 0; k0 < 256; k0 += 16) {
        float4 va = *(const float4*)&Aao[(m0 + lr) * 256 + k0 + lc4];
        As[lr][lc4 + 0] = va.x; As[lr][lc4 + 1] = va.y;
        As[lr][lc4 + 2] = va.z; As[lr][lc4 + 3] = va.w;
        float4 vw = *(const float4*)&Wp[(n0 + lr) * 256 + k0 + lc4];
        Ws[lr][lc4 + 0] = vw.x; Ws[lr][lc4 + 1] = vw.y;
        Ws[lr][lc4 + 2] = vw.z; Ws[lr][lc4 + 3] = vw.w;
        __syncthreads();

        #pragma unroll
        for (int kk = 0; kk < 16; kk++) {
            float af[4], wf[4];
            #pragma unroll
            for (int i = 0; i < 4; i++) af[i] = As[tx * 4 + i][kk];
            #pragma unroll
            for (int j = 0; j < 4; j++) wf[j] = Ws[ty * 4 + j][kk];
            #pragma unroll
            for (int i = 0; i < 4; i++)
                #pragma unroll
                for (int j = 0; j < 4; j++) acc[i][j] += af[i] * wf[j];
        }
        __syncthreads();
    }

    int mrow = m0 + tx * 4;            // 4 consecutive l, same b (LL % 64 == 0)
    int b = mrow / LL, l0 = mrow % LL;
    #pragma unroll
    for (int j = 0; j < 4; j++) {
        int cc = n0 + ty * 4 + j;
        float bb = bp[cc];
        long base = (long)(b * CH + cc) * LL + l0;
        float4 rx = *(const float4*)&x[base];
        float4 r;
        r.x = acc[0][j] + bb + rx.x;
        r.y = acc[1][j] + bb + rx.y;
        r.z = acc[2][j] + bb + rx.z;
        r.w = acc[3][j] + bb + rx.w;
        *(float4*)&out[base] = r;
    }
}

// ============================================================
extern "C" void kernel_launch(void* const* d_in, const int* in_sizes, int n_in,
                              void* d_out, int out_size) {
    const float* x    = (const float*)d_in[0];
    const float* ctx  = (const float*)d_in[1];
    const float* lnxw = (const float*)d_in[2];
    const float* lnxb = (const float*)d_in[3];
    const float* lncw = (const float*)d_in[4];
    const float* lncb = (const float*)d_in[5];
    const float* Wq   = (const float*)d_in[6];
    const float* bq   = (const float*)d_in[7];
    const float* Wk   = (const float*)d_in[8];
    const float* bk   = (const float*)d_in[9];
    const float* Wv   = (const float*)d_in[10];
    const float* bv   = (const float*)d_in[11];
    const float* Wp   = (const float*)d_in[12];
    const float* bp   = (const float*)d_in[13];
    const float* relt = (const float*)d_in[14];
    float* out = (float*)d_out;

    float *p_xn, *p_cn, *p_q, *p_k, *p_v, *p_ao;
    cudaGetSymbolAddress((void**)&p_xn, g_xn);
    cudaGetSymbolAddress((void**)&p_cn, g_cn);
    cudaGetSymbolAddress((void**)&p_q,  g_q);
    cudaGetSymbolAddress((void**)&p_k,  g_k);
    cudaGetSymbolAddress((void**)&p_v,  g_v);
    cudaGetSymbolAddress((void**)&p_ao, g_ao);

    // 1) layernorms
    ln_kernel<<<BATCH * LL, 256>>>(x,   lnxw, lnxb, p_xn);
    ln_kernel<<<BATCH * LL, 256>>>(ctx, lncw, lncb, p_cn);

    // 2) Q/K/V projections
    dim3 gproj(BATCH * LL / 64, INNER / 64);
    proj_qkv_kernel<<<gproj, 256>>>(p_xn, Wq, bq, p_q);
    proj_qkv_kernel<<<gproj, 256>>>(p_cn, Wk, bk, p_k);
    proj_qkv_kernel<<<gproj, 256>>>(p_cn, Wv, bv, p_v);

    // 3) flash attention with relative bias
    dim3 gattn(LL / 128, HEADS, BATCH);
    attn_kernel<<<gattn, 128>>>(p_q, p_k, p_v, relt, p_ao);

    // 4) output projection + residual
    dim3 gout(BATCH * LL / 64, CH / 64);
    proj_out_kernel<<<gout, 256>>>(p_ao, Wp, bp, x, out);
}

// round 4
// speedup vs baseline: 3.0146x; 3.0146x over previous
#include <cuda_runtime.h>
#include <cuda_bf16.h>
#include <cstdint>
#include <stdint.h>

// ---------------- problem constants ----------------
#define BATCH 4
#define CH    256
#define HH    48
#define WW    48
#define LL    2304          // HH*WW
#define HEADS 8
#define HD    32
#define INNER 256           // HEADS*HD
#define SCALE 0.17677669529663687f   // 1/sqrt(32)

// ---------------- scratch (static device allocations; no cudaMalloc) ------
__device__ float          g_xn[BATCH * LL * CH];          // normalized x,   [b][l][c]
__device__ float          g_cn[BATCH * LL * CH];          // normalized ctx, [b][l][c]
__device__ __align__(16) __nv_bfloat16  g_q [BATCH * HEADS * LL * HD];  // [b][h][l][d] (pre-scaled)
__device__ __align__(16) __nv_bfloat16  g_k [BATCH * HEADS * LL * HD];  // [b][h][l][d]
__device__ __align__(16) __nv_bfloat16  g_v [BATCH * HEADS * HD * LL];  // [b][h][d][l] (transposed!)
__device__ float          g_ao[BATCH * LL * INNER];       // attention out, [b][l][o]
__device__ float          g_bias[HEADS * 95 * 95];        // compact per-head bias

// ---------------- helpers ----------------
__device__ __forceinline__ uint32_t packbf(float lo, float hi) {
    __nv_bfloat162 p = __floats2bfloat162_rn(lo, hi);   // x=lo (low 16b), y=hi
    return *(uint32_t*)&p;
}

__device__ __forceinline__ void mma_bf16(float4& c, const uint32_t a[4],
                                         uint32_t b0, uint32_t b1) {
    asm volatile(
        "mma.sync.aligned.m16n8k16.row.col.f32.bf16.bf16.f32 "
        "{%0,%1,%2,%3}, {%4,%5,%6,%7}, {%8,%9}, {%0,%1,%2,%3};\n"
        : "+f"(c.x), "+f"(c.y), "+f"(c.z), "+f"(c.w)
        : "r"(a[0]), "r"(a[1]), "r"(a[2]), "r"(a[3]), "r"(b0), "r"(b1));
}

// ============================================================
// Bias precompute: g_bias[h][dy+47][dx+47], dy,dx in [-47,47]
// ============================================================
__global__ void bias_prep_kernel(const float* __restrict__ rel_table,
                                 float* __restrict__ out) {
    int i = blockIdx.x * 256 + threadIdx.x;
    if (i < HEADS * 95 * 95) {
        int h = i / (95 * 95), r = i % (95 * 95);
        int dy = r / 95, dx = r % 95;
        // table index: (rel_y + 63)*127 + (rel_x + 63); rel = dy-47 -> dy+16
        out[i] = rel_table[((dy + 16) * 127 + (dx + 16)) * HEADS + h];
    }
}

// ============================================================
// LayerNorm over channels: src [b][c][l]  ->  dst [b][l][c]
// ============================================================
__global__ void ln_kernel(const float* __restrict__ src,
                          const float* __restrict__ w,
                          const float* __restrict__ bia,
                          float* __restrict__ dst) {
    int p = blockIdx.x;
    int b = p / LL, l = p % LL;
    int c = threadIdx.x;

    float v = src[(b * CH + c) * LL + l];

    __shared__ float s1[8], s2[8];
    float a = v, q = v * v;
    #pragma unroll
    for (int o = 16; o > 0; o >>= 1) {
        a += __shfl_xor_sync(0xFFFFFFFFu, a, o);
        q += __shfl_xor_sync(0xFFFFFFFFu, q, o);
    }
    if ((c & 31) == 0) { s1[c >> 5] = a; s2[c >> 5] = q; }
    __syncthreads();
    float suma = 0.f, sumq = 0.f;
    #pragma unroll
    for (int i = 0; i < 8; i++) { suma += s1[i]; sumq += s2[i]; }

    float mu  = suma * (1.0f / 256.0f);
    float var = sumq * (1.0f / 256.0f) - mu * mu;
    float inv = rsqrtf(var + 1e-6f);

    dst[p * CH + c] = (v - mu) * inv * w[c] + bia[c];
}

// ============================================================
// QKV projection GEMM -> bf16 outputs.
//   MODE 0: Q  -> [b][h][l][d], scaled by 1/sqrt(HD)
//   MODE 1: K  -> [b][h][l][d]
//   MODE 2: V  -> [b][h][d][l]   (transposed for attention smem tiles)
// ============================================================
template<int MODE>
__global__ void proj_qkv_bf16(const float* __restrict__ A,
                              const float* __restrict__ W,
                              const float* __restrict__ bias,
                              __nv_bfloat16* __restrict__ out) {
    __shared__ float As[64][17];
    __shared__ float Ws[64][17];

    int m0 = blockIdx.x * 64;
    int n0 = blockIdx.y * 64;
    int tid = threadIdx.x;
    int tx = tid & 15, ty = tid >> 4;

    float acc[4][4];
    #pragma unroll
    for (int i = 0; i < 4; i++)
        #pragma unroll
        for (int j = 0; j < 4; j++) acc[i][j] = 0.f;

    int lr  = tid >> 2;
    int lc4 = (tid & 3) * 4;

    for (int k0 = 0; k0 < 256; k0 += 16) {
        float4 va = *(const float4*)&A[(m0 + lr) * 256 + k0 + lc4];
        As[lr][lc4 + 0] = va.x; As[lr][lc4 + 1] = va.y;
        As[lr][lc4 + 2] = va.z; As[lr][lc4 + 3] = va.w;
        float4 vw = *(const float4*)&W[(n0 + lr) * 256 + k0 + lc4];
        Ws[lr][lc4 + 0] = vw.x; Ws[lr][lc4 + 1] = vw.y;
        Ws[lr][lc4 + 2] = vw.z; Ws[lr][lc4 + 3] = vw.w;
        __syncthreads();

        #pragma unroll
        for (int kk = 0; kk < 16; kk++) {
            float af[4], wf[4];
            #pragma unroll
            for (int i = 0; i < 4; i++) af[i] = As[ty * 4 + i][kk];
            #pragma unroll
            for (int j = 0; j < 4; j++) wf[j] = Ws[tx * 4 + j][kk];
            #pragma unroll
            for (int i = 0; i < 4; i++)
                #pragma unroll
                for (int j = 0; j < 4; j++) acc[i][j] += af[i] * wf[j];
        }
        __syncthreads();
    }

    int o0 = n0 + tx * 4;
    int h  = o0 >> 5, d0 = o0 & 31;
    const float sc = (MODE == 0) ? SCALE : 1.0f;

    if (MODE < 2) {
        #pragma unroll
        for (int i = 0; i < 4; i++) {
            int m = m0 + ty * 4 + i;
            int b = m / LL, l = m % LL;
            float f0 = (acc[i][0] + bias[o0 + 0]) * sc;
            float f1 = (acc[i][1] + bias[o0 + 1]) * sc;
            float f2 = (acc[i][2] + bias[o0 + 2]) * sc;
            float f3 = (acc[i][3] + bias[o0 + 3]) * sc;
            uint2 u;
            u.x = packbf(f0, f1);
            u.y = packbf(f2, f3);
            *(uint2*)&out[((size_t)((b * HEADS + h) * LL) + l) * HD + d0] = u;
        }
    } else {
        // V transposed: out[b][h][d][l]; 4 consecutive l per store (same b)
        int m = m0 + ty * 4;
        int b = m / LL, l0 = m % LL;
        #pragma unroll
        for (int j = 0; j < 4; j++) {
            int d = d0 + j;
            float f0 = acc[0][j] + bias[o0 + j];
            float f1 = acc[1][j] + bias[o0 + j];
            float f2 = acc[2][j] + bias[o0 + j];
            float f3 = acc[3][j] + bias[o0 + j];
            uint2 u;
            u.x = packbf(f0, f1);
            u.y = packbf(f2, f3);
            *(uint2*)&out[((size_t)(b * HEADS + h) * HD + d) * LL + l0] = u;
        }
    }
}

// ============================================================
// Flash attention v2 with mma.sync bf16 tensor cores.
// 4 warps / block, 16 queries per warp (64 / block), 64-key tiles.
// K smem [key][dim] (stride 40 halfs), V smem [dim][key] (stride 72 halfs)
// -> conflict-free LDS.32 B-fragment loads.
// NOTE: smem arrays are __align__(16) — sb is 36,100 bytes (not 16B-multiple)
// and ksm/vsm take STS.128; without the attribute their base lands at
// offset%16==4 -> misaligned-address trap (round-3 failure).
// ============================================================
__global__ void __launch_bounds__(128)
attn_mma_kernel(const __nv_bfloat16* __restrict__ q,
                const __nv_bfloat16* __restrict__ k,
                const __nv_bfloat16* __restrict__ v,
                const float* __restrict__ biasc,
                float* __restrict__ ao) {
    __shared__ __align__(16) float sb[95 * 95];               // 36.1 KB
    __shared__ __align__(16) __nv_bfloat16 ksm[64][40];       // 5.0 KB
    __shared__ __align__(16) __nv_bfloat16 vsm[32][72];       // 4.5 KB

    int b = blockIdx.z, h = blockIdx.y;
    int q0 = blockIdx.x * 64;
    int t = threadIdx.x;
    int w = t >> 5, lane = t & 31;
    int g = lane >> 2, tg = lane & 3;

    // per-head bias table into smem (coalesced, L2-resident source)
    const float* bh = biasc + h * 9025;
    for (int i = t; i < 9025; i += 128) sb[i] = bh[i];

    // Q fragments (A of m16n8k16): rows g,g+8; cols tg*2 + {0,8} per k-step
    const __nv_bfloat16* qb = q + ((size_t)(b * HEADS + h) * LL + q0 + w * 16) * HD;
    uint32_t qf[2][4];
    #pragma unroll
    for (int s2 = 0; s2 < 2; s2++) {
        int d0 = s2 * 16 + tg * 2;
        qf[s2][0] = *(const uint32_t*)(qb + (size_t)g       * HD + d0);
        qf[s2][1] = *(const uint32_t*)(qb + (size_t)(g + 8) * HD + d0);
        qf[s2][2] = *(const uint32_t*)(qb + (size_t)g       * HD + d0 + 8);
        qf[s2][3] = *(const uint32_t*)(qb + (size_t)(g + 8) * HD + d0 + 8);
    }

    int qi0 = q0 + w * 16 + g;
    int qi1 = qi0 + 8;
    int base0 = (qi0 / WW + 47) * 95 + (qi0 % WW) + 47;
    int base1 = (qi1 / WW + 47) * 95 + (qi1 % WW) + 47;

    float4 o[4];
    #pragma unroll
    for (int nt = 0; nt < 4; nt++) o[nt] = make_float4(0.f, 0.f, 0.f, 0.f);
    float mx0 = -1e30f, mx1 = -1e30f, ls0 = 0.f, ls1 = 0.f;

    const __nv_bfloat16* kb = k + (size_t)(b * HEADS + h) * LL * HD;
    const __nv_bfloat16* vb = v + (size_t)(b * HEADS + h) * HD * LL;

    for (int j0 = 0; j0 < LL; j0 += 64) {
        __syncthreads();   // previous tile fully consumed (also fences bias load on iter 0)
        // stage K tile: 64 keys x 32 dims (each thread: 16 halfs of one row)
        {
            int row = t >> 1, c0 = (t & 1) * 16;
            const uint4* src = (const uint4*)(kb + (size_t)(j0 + row) * HD + c0);
            uint4 u0 = src[0], u1 = src[1];
            *(uint4*)&ksm[row][c0]     = u0;
            *(uint4*)&ksm[row][c0 + 8] = u1;
        }
        // stage V tile: 32 dims x 64 keys
        {
            #pragma unroll
            for (int rep = 0; rep < 2; rep++) {
                int i = t + rep * 128;
                int row = i >> 3, c = (i & 7) * 8;
                uint4 u = *(const uint4*)(vb + (size_t)row * LL + j0 + c);
                *(uint4*)&vsm[row][c] = u;
            }
        }
        __syncthreads();

        // ---- S = Q K^T (+bias), online max ----
        float s[8][4];
        float mt0 = -1e30f, mt1 = -1e30f;
        #pragma unroll
        for (int nt = 0; nt < 8; nt++) {
            int key = nt * 8 + g;
            uint32_t b00 = *(const uint32_t*)&ksm[key][tg * 2];
            uint32_t b01 = *(const uint32_t*)&ksm[key][tg * 2 + 8];
            uint32_t b10 = *(const uint32_t*)&ksm[key][tg * 2 + 16];
            uint32_t b11 = *(const uint32_t*)&ksm[key][tg * 2 + 24];
            float4 acc = make_float4(0.f, 0.f, 0.f, 0.f);
            mma_bf16(acc, qf[0], b00, b01);
            mma_bf16(acc, qf[1], b10, b11);

            int kj  = j0 + nt * 8 + tg * 2;
            int y0  = kj / WW,  x0 = kj - y0 * WW;
            int kj1 = kj + 1;
            int y1  = kj1 / WW, x1 = kj1 - y1 * WW;
            int c0i = y0 * 95 + x0, c1i = y1 * 95 + x1;

            float s0 = acc.x + sb[base0 - c0i];
            float s1 = acc.y + sb[base0 - c1i];
            float s2 = acc.z + sb[base1 - c0i];
            float s3 = acc.w + sb[base1 - c1i];
            s[nt][0] = s0; s[nt][1] = s1; s[nt][2] = s2; s[nt][3] = s3;
            mt0 = fmaxf(mt0, fmaxf(s0, s1));
            mt1 = fmaxf(mt1, fmaxf(s2, s3));
        }
        // row max across the 4-thread quad
        mt0 = fmaxf(mt0, __shfl_xor_sync(0xFFFFFFFFu, mt0, 1));
        mt0 = fmaxf(mt0, __shfl_xor_sync(0xFFFFFFFFu, mt0, 2));
        mt1 = fmaxf(mt1, __shfl_xor_sync(0xFFFFFFFFu, mt1, 1));
        mt1 = fmaxf(mt1, __shfl_xor_sync(0xFFFFFFFFu, mt1, 2));

        float nm0 = fmaxf(mx0, mt0), nm1 = fmaxf(mx1, mt1);
        float cr0 = __expf(mx0 - nm0), cr1 = __expf(mx1 - nm1);
        mx0 = nm0; mx1 = nm1;
        ls0 *= cr0; ls1 *= cr1;
        #pragma unroll
        for (int nt = 0; nt < 4; nt++) {
            o[nt].x *= cr0; o[nt].y *= cr0;   // row g
            o[nt].z *= cr1; o[nt].w *= cr1;   // row g+8
        }

        // ---- P = exp(S - m), packed straight into A fragments ----
        uint32_t pA[4][4];
        #pragma unroll
        for (int ks2 = 0; ks2 < 4; ks2++) {
            int ntA = 2 * ks2, ntB = 2 * ks2 + 1;
            float pa0 = __expf(s[ntA][0] - nm0), pa1 = __expf(s[ntA][1] - nm0);
            float pa2 = __expf(s[ntA][2] - nm1), pa3 = __expf(s[ntA][3] - nm1);
            float pb0 = __expf(s[ntB][0] - nm0), pb1 = __expf(s[ntB][1] - nm0);
            float pb2 = __expf(s[ntB][2] - nm1), pb3 = __expf(s[ntB][3] - nm1);
            ls0 += pa0 + pa1 + pb0 + pb1;
            ls1 += pa2 + pa3 + pb2 + pb3;
            pA[ks2][0] = packbf(pa0, pa1);   // ntA, row g
            pA[ks2][1] = packbf(pa2, pa3);   // ntA, row g+8
            pA[ks2][2] = packbf(pb0, pb1);   // ntB, row g
            pA[ks2][3] = packbf(pb2, pb3);   // ntB, row g+8
        }

        // ---- O += P V ----
        #pragma unroll
        for (int ks2 = 0; ks2 < 4; ks2++) {
            #pragma unroll
            for (int nt = 0; nt < 4; nt++) {
                uint32_t v0 = *(const uint32_t*)&vsm[nt * 8 + g][ks2 * 16 + tg * 2];
                uint32_t v1 = *(const uint32_t*)&vsm[nt * 8 + g][ks2 * 16 + tg * 2 + 8];
                mma_bf16(o[nt], pA[ks2], v0, v1);
            }
        }
    }

    // final row-sum reduce + normalize + store
    ls0 += __shfl_xor_sync(0xFFFFFFFFu, ls0, 1);
    ls0 += __shfl_xor_sync(0xFFFFFFFFu, ls0, 2);
    ls1 += __shfl_xor_sync(0xFFFFFFFFu, ls1, 1);
    ls1 += __shfl_xor_sync(0xFFFFFFFFu, ls1, 2);
    float i0 = 1.0f / ls0, i1 = 1.0f / ls1;

    float* o0p = ao + ((size_t)(b * LL) + qi0) * INNER + h * HD;
    float* o1p = ao + ((size_t)(b * LL) + qi1) * INNER + h * HD;
    #pragma unroll
    for (int nt = 0; nt < 4; nt++) {
        float2 r0 = make_float2(o[nt].x * i0, o[nt].y * i0);
        float2 r1 = make_float2(o[nt].z * i1, o[nt].w * i1);
        *(float2*)&o0p[nt * 8 + tg * 2] = r0;
        *(float2*)&o1p[nt * 8 + tg * 2] = r1;
    }
}

// ============================================================
// Output projection + residual:
//   out[b][c][l] = x[b][c][l] + bp[c] + sum_o Wp[c][o] * ao[b][l][o]
// ============================================================
__global__ void proj_out_kernel(const float* __restrict__ Aao,
                                const float* __restrict__ Wp,
                                const float* __restrict__ bp,
                                const float* __restrict__ x,
                                float* __restrict__ out) {
    __shared__ float As[64][17];
    __shared__ float Ws[64][17];

    int m0 = blockIdx.x * 64;
    int n0 = blockIdx.y * 64;
    int tid = threadIdx.x;
    int tx = tid & 15, ty = tid >> 4;

    float acc[4][4];
    #pragma unroll
    for (int i = 0; i < 4; i++)
        #pragma unroll
        for (int j = 0; j < 4; j++) acc[i][j] = 0.f;

    int lr  = tid >> 2;
    int lc4 = (tid & 3) * 4;

    for (int k0 = 0; k0 < 256; k0 += 16) {
        float4 va = *(const float4*)&Aao[(m0 + lr) * 256 + k0 + lc4];
        As[lr][lc4 + 0] = va.x; As[lr][lc4 + 1] = va.y;
        As[lr][lc4 + 2] = va.z; As[lr][lc4 + 3] = va.w;
        float4 vw = *(const float4*)&Wp[(n0 + lr) * 256 + k0 + lc4];
        Ws[lr][lc4 + 0] = vw.x; Ws[lr][lc4 + 1] = vw.y;
        Ws[lr][lc4 + 2] = vw.z; Ws[lr][lc4 + 3] = vw.w;
        __syncthreads();

        #pragma unroll
        for (int kk = 0; kk < 16; kk++) {
            float af[4], wf[4];
            #pragma unroll
            for (int i = 0; i < 4; i++) af[i] = As[tx * 4 + i][kk];
            #pragma unroll
            for (int j = 0; j < 4; j++) wf[j] = Ws[ty * 4 + j][kk];
            #pragma unroll
            for (int i = 0; i < 4; i++)
                #pragma unroll
                for (int j = 0; j < 4; j++) acc[i][j] += af[i] * wf[j];
        }
        __syncthreads();
    }

    int mrow = m0 + tx * 4;
    int b = mrow / LL, l0 = mrow % LL;
    #pragma unroll
    for (int j = 0; j < 4; j++) {
        int cc = n0 + ty * 4 + j;
        float bb = bp[cc];
        long base = (long)(b * CH + cc) * LL + l0;
        float4 rx = *(const float4*)&x[base];
        float4 r;
        r.x = acc[0][j] + bb + rx.x;
        r.y = acc[1][j] + bb + rx.y;
        r.z = acc[2][j] + bb + rx.z;
        r.w = acc[3][j] + bb + rx.w;
        *(float4*)&out[base] = r;
    }
}

// ============================================================
extern "C" void kernel_launch(void* const* d_in, const int* in_sizes, int n_in,
                              void* d_out, int out_size) {
    const float* x    = (const float*)d_in[0];
    const float* ctx  = (const float*)d_in[1];
    const float* lnxw = (const float*)d_in[2];
    const float* lnxb = (const float*)d_in[3];
    const float* lncw = (const float*)d_in[4];
    const float* lncb = (const float*)d_in[5];
    const float* Wq   = (const float*)d_in[6];
    const float* bq   = (const float*)d_in[7];
    const float* Wk   = (const float*)d_in[8];
    const float* bk   = (const float*)d_in[9];
    const float* Wv   = (const float*)d_in[10];
    const float* bv   = (const float*)d_in[11];
    const float* Wp   = (const float*)d_in[12];
    const float* bp   = (const float*)d_in[13];
    const float* relt = (const float*)d_in[14];
    float* out = (float*)d_out;

    float *p_xn, *p_cn, *p_ao, *p_bias;
    __nv_bfloat16 *p_q, *p_k, *p_v;
    cudaGetSymbolAddress((void**)&p_xn, g_xn);
    cudaGetSymbolAddress((void**)&p_cn, g_cn);
    cudaGetSymbolAddress((void**)&p_q,  g_q);
    cudaGetSymbolAddress((void**)&p_k,  g_k);
    cudaGetSymbolAddress((void**)&p_v,  g_v);
    cudaGetSymbolAddress((void**)&p_ao, g_ao);
    cudaGetSymbolAddress((void**)&p_bias, g_bias);

    // 0) compact bias table
    bias_prep_kernel<<<(HEADS * 95 * 95 + 255) / 256, 256>>>(relt, p_bias);

    // 1) layernorms
    ln_kernel<<<BATCH * LL, 256>>>(x,   lnxw, lnxb, p_xn);
    ln_kernel<<<BATCH * LL, 256>>>(ctx, lncw, lncb, p_cn);

    // 2) Q/K/V projections -> bf16
    dim3 gproj(BATCH * LL / 64, INNER / 64);
    proj_qkv_bf16<0><<<gproj, 256>>>(p_xn, Wq, bq, p_q);
    proj_qkv_bf16<1><<<gproj, 256>>>(p_cn, Wk, bk, p_k);
    proj_qkv_bf16<2><<<gproj, 256>>>(p_cn, Wv, bv, p_v);

    // 3) tensor-core flash attention with relative bias
    dim3 gattn(LL / 64, HEADS, BATCH);
    attn_mma_kernel<<<gattn, 128>>>(p_q, p_k, p_v, p_bias, p_ao);

    // 4) output projection + residual
    dim3 gout(BATCH * LL / 64, CH / 64);
    proj_out_kernel<<<gout, 256>>>(p_ao, Wp, bp, x, out);
}

// round 6
// speedup vs baseline: 4.9240x; 1.6334x over previous
#include <cuda_runtime.h>
#include <cuda_bf16.h>
#include <cstdint>
#include <stdint.h>

// ---------------- problem constants ----------------
#define BATCH 4
#define CH    256
#define HH    48
#define WW    48
#define LL    2304          // HH*WW
#define HEADS 8
#define HD    32
#define INNER 256           // HEADS*HD
#define SCALE 0.17677669529663687f   // 1/sqrt(32)

// ---------------- scratch (static device allocations; no cudaMalloc) ------
__device__ __align__(16) __nv_bfloat16 g_xnb[BATCH * LL * CH];         // ln(x)   [b][l][c]
__device__ __align__(16) __nv_bfloat16 g_cnb[BATCH * LL * CH];         // ln(ctx) [b][l][c]
__device__ __align__(16) __nv_bfloat16 g_q [BATCH * HEADS * LL * HD];  // [b][h][l][d] (pre-scaled)
__device__ __align__(16) __nv_bfloat16 g_k [BATCH * HEADS * LL * HD];  // [b][h][l][d]
__device__ __align__(16) __nv_bfloat16 g_v [BATCH * HEADS * LL * HD];  // [b][h][l][d] (same as K)
__device__ __align__(16) __nv_bfloat16 g_ao[BATCH * LL * INNER];       // attention out bf16
__device__ __align__(16) __nv_bfloat16 g_wq[CH * INNER];
__device__ __align__(16) __nv_bfloat16 g_wk[CH * INNER];
__device__ __align__(16) __nv_bfloat16 g_wv[CH * INNER];
__device__ __align__(16) __nv_bfloat16 g_wp[CH * INNER];
__device__ float g_bias[HEADS * 95 * 95];                              // compact per-head bias

// ---------------- helpers ----------------
__device__ __forceinline__ uint32_t packbf(float lo, float hi) {
    __nv_bfloat162 p = __floats2bfloat162_rn(lo, hi);
    return *(uint32_t*)&p;
}

__device__ __forceinline__ void mma_bf16(float4& c, const uint32_t a[4],
                                         uint32_t b0, uint32_t b1) {
    asm volatile(
        "mma.sync.aligned.m16n8k16.row.col.f32.bf16.bf16.f32 "
        "{%0,%1,%2,%3}, {%4,%5,%6,%7}, {%8,%9}, {%0,%1,%2,%3};\n"
        : "+f"(c.x), "+f"(c.y), "+f"(c.z), "+f"(c.w)
        : "r"(a[0]), "r"(a[1]), "r"(a[2]), "r"(a[3]), "r"(b0), "r"(b1));
}

__device__ __forceinline__ void ldsm_x4_trans(uint32_t& r0, uint32_t& r1,
                                              uint32_t& r2, uint32_t& r3,
                                              uint32_t saddr) {
    asm volatile(
        "ldmatrix.sync.aligned.m8n8.x4.trans.shared.b16 {%0,%1,%2,%3}, [%4];\n"
        : "=r"(r0), "=r"(r1), "=r"(r2), "=r"(r3) : "r"(saddr));
}

// ============================================================
// Weight fp32 -> bf16 conversion (once per launch graph)
// ============================================================
__global__ void wconv_kernel(const float* __restrict__ a, const float* __restrict__ b,
                             const float* __restrict__ c, const float* __restrict__ d,
                             __nv_bfloat16* __restrict__ oa, __nv_bfloat16* __restrict__ ob,
                             __nv_bfloat16* __restrict__ oc, __nv_bfloat16* __restrict__ od) {
    int i = blockIdx.x * 256 + threadIdx.x;   // 65536 total
    oa[i] = __float2bfloat16(a[i]);
    ob[i] = __float2bfloat16(b[i]);
    oc[i] = __float2bfloat16(c[i]);
    od[i] = __float2bfloat16(d[i]);
}

// ============================================================
// Bias precompute: g_bias[h][dy+47][dx+47], dy,dx in [-47,47]
// ============================================================
__global__ void bias_prep_kernel(const float* __restrict__ rel_table,
                                 float* __restrict__ out) {
    int i = blockIdx.x * 256 + threadIdx.x;
    if (i < HEADS * 95 * 95) {
        int h = i / (95 * 95), r = i % (95 * 95);
        int dy = r / 95, dx = r % 95;
        out[i] = rel_table[((dy + 16) * 127 + (dx + 16)) * HEADS + h];
    }
}

// ============================================================
// LayerNorm over channels: src [b][c][l] -> dst bf16 [b][l][c]
// ============================================================
__global__ void ln_kernel(const float* __restrict__ src,
                          const float* __restrict__ w,
                          const float* __restrict__ bia,
                          __nv_bfloat16* __restrict__ dst) {
    int p = blockIdx.x;
    int b = p / LL, l = p % LL;
    int c = threadIdx.x;

    float v = src[(b * CH + c) * LL + l];

    __shared__ float s1[8], s2[8];
    float a = v, q = v * v;
    #pragma unroll
    for (int o = 16; o > 0; o >>= 1) {
        a += __shfl_xor_sync(0xFFFFFFFFu, a, o);
        q += __shfl_xor_sync(0xFFFFFFFFu, q, o);
    }
    if ((c & 31) == 0) { s1[c >> 5] = a; s2[c >> 5] = q; }
    __syncthreads();
    float suma = 0.f, sumq = 0.f;
    #pragma unroll
    for (int i = 0; i < 8; i++) { suma += s1[i]; sumq += s2[i]; }

    float mu  = suma * (1.0f / 256.0f);
    float var = sumq * (1.0f / 256.0f) - mu * mu;
    float inv = rsqrtf(var + 1e-6f);

    dst[p * CH + c] = __float2bfloat16((v - mu) * inv * w[c] + bia[c]);
}

// ============================================================
// Tensor-core GEMM: C[M=9216][N] = A[M][256] * W[N][256]^T (+bias)
// MODE 0: Q epilogue (scale, bf16 out [b][h][l][d])
// MODE 1: K/V epilogue (bf16 out [b][h][l][d])
// MODE 3: out-proj epilogue (fp32 out [b][c][l] + residual, via smem transpose)
// Block: 256 thr = 8 warps (4 m x 2 n), tile 128x64, K slabs of 64.
// ============================================================
template<int MODE>
__global__ void __launch_bounds__(256) gemm_mma(
    const __nv_bfloat16* __restrict__ A,
    const __nv_bfloat16* __restrict__ W,
    const float* __restrict__ bias,
    const float* __restrict__ xres,
    void* __restrict__ outp) {
    constexpr int SMB = (MODE == 3) ? 34048 : 27648;
    __shared__ __align__(16) char smraw[SMB];
    __nv_bfloat16 (*As)[72] = (__nv_bfloat16(*)[72])smraw;
    __nv_bfloat16 (*Ws)[72] = (__nv_bfloat16(*)[72])(smraw + 128 * 72 * 2);

    int m0 = blockIdx.x * 128, n0 = blockIdx.y * 64;
    int tid = threadIdx.x;
    int w = tid >> 5, lane = tid & 31, g = lane >> 2, tg = lane & 3;
    int wm = (w & 3) * 32, wn = (w >> 2) * 32;

    float4 acc[2][4];
    #pragma unroll
    for (int mf = 0; mf < 2; mf++)
        #pragma unroll
        for (int nf = 0; nf < 4; nf++) acc[mf][nf] = make_float4(0.f, 0.f, 0.f, 0.f);

    for (int k0 = 0; k0 < 256; k0 += 64) {
        __syncthreads();
        #pragma unroll
        for (int i = 0; i < 4; i++) {
            int idx = tid + i * 256;
            int r = idx >> 3, c8 = (idx & 7) * 8;
            *(uint4*)&As[r][c8] = *(const uint4*)&A[(size_t)(m0 + r) * 256 + k0 + c8];
        }
        #pragma unroll
        for (int i = 0; i < 2; i++) {
            int idx = tid + i * 256;
            int r = idx >> 3, c8 = (idx & 7) * 8;
            *(uint4*)&Ws[r][c8] = *(const uint4*)&W[(size_t)(n0 + r) * 256 + k0 + c8];
        }
        __syncthreads();

        #pragma unroll
        for (int kk = 0; kk < 4; kk++) {
            uint32_t af[2][4];
            #pragma unroll
            for (int mf = 0; mf < 2; mf++) {
                int r = wm + mf * 16 + g;
                af[mf][0] = *(const uint32_t*)&As[r    ][kk * 16 + tg * 2];
                af[mf][1] = *(const uint32_t*)&As[r + 8][kk * 16 + tg * 2];
                af[mf][2] = *(const uint32_t*)&As[r    ][kk * 16 + tg * 2 + 8];
                af[mf][3] = *(const uint32_t*)&As[r + 8][kk * 16 + tg * 2 + 8];
            }
            #pragma unroll
            for (int nf = 0; nf < 4; nf++) {
                int rn = wn + nf * 8 + g;
                uint32_t b0 = *(const uint32_t*)&Ws[rn][kk * 16 + tg * 2];
                uint32_t b1 = *(const uint32_t*)&Ws[rn][kk * 16 + tg * 2 + 8];
                mma_bf16(acc[0][nf], af[0], b0, b1);
                mma_bf16(acc[1][nf], af[1], b0, b1);
            }
        }
    }

    if (MODE != 3) {
        const float sc = (MODE == 0) ? SCALE : 1.0f;
        __nv_bfloat16* out = (__nv_bfloat16*)outp;
        #pragma unroll
        for (int mf = 0; mf < 2; mf++) {
            int m = m0 + wm + mf * 16 + g;
            int bb = m / LL, l = m % LL;       // m, m+8 in same batch (LL % 128 == 0)
            #pragma unroll
            for (int nf = 0; nf < 4; nf++) {
                int col = n0 + wn + nf * 8 + tg * 2;
                int h = col >> 5, d = col & 31;
                float bs0 = bias[col], bs1 = bias[col + 1];
                float4 c = acc[mf][nf];
                uint32_t lo = packbf((c.x + bs0) * sc, (c.y + bs1) * sc);
                uint32_t hi = packbf((c.z + bs0) * sc, (c.w + bs1) * sc);
                size_t base = (size_t)(bb * HEADS + h) * LL;
                *(uint32_t*)&out[(base + l    ) * HD + d] = lo;
                *(uint32_t*)&out[(base + l + 8) * HD + d] = hi;
            }
        }
    } else {
        float (*Ct)[132] = (float(*)[132])smraw;   // [c 0..63][l 0..127(+4 pad)]
        __syncthreads();                            // done reading As/Ws
        #pragma unroll
        for (int mf = 0; mf < 2; mf++) {
            int ml = wm + mf * 16 + g;
            #pragma unroll
            for (int nf = 0; nf < 4; nf++) {
                int cn = wn + nf * 8 + tg * 2;
                float4 c = acc[mf][nf];
                Ct[cn    ][ml    ] = c.x;
                Ct[cn + 1][ml    ] = c.y;
                Ct[cn    ][ml + 8] = c.z;
                Ct[cn + 1][ml + 8] = c.w;
            }
        }
        __syncthreads();
        float* out = (float*)outp;
        int b_ = m0 / LL, l0 = m0 % LL;
        #pragma unroll
        for (int i = 0; i < 8; i++) {
            int idx = tid + i * 256;
            int cr = idx >> 5, l4 = (idx & 31) * 4;
            int col = n0 + cr;
            size_t gaddr = (size_t)(b_ * CH + col) * LL + l0 + l4;
            float4 rx = *(const float4*)&xres[gaddr];
            float bb = bias[col];
            float4 r;
            r.x = Ct[cr][l4 + 0] + bb + rx.x;
            r.y = Ct[cr][l4 + 1] + bb + rx.y;
            r.z = Ct[cr][l4 + 2] + bb + rx.z;
            r.w = Ct[cr][l4 + 3] + bb + rx.w;
            *(float4*)&out[gaddr] = r;
        }
    }
}

// ============================================================
// Flash attention v2 with mma.sync bf16 tensor cores.
// 4 warps / block, 16 queries per warp (64/block), 64-key tiles.
// K,V smem [key][dim] stride 40 halfs; V^T fragments via ldmatrix.x4.trans
// (rows are 80 B apart = 16B-aligned, conflict-free 8-row phases).
// ============================================================
__global__ void __launch_bounds__(128)
attn_mma_kernel(const __nv_bfloat16* __restrict__ q,
                const __nv_bfloat16* __restrict__ k,
                const __nv_bfloat16* __restrict__ v,
                const float* __restrict__ biasc,
                __nv_bfloat16* __restrict__ ao) {
    __shared__ __align__(16) float sb[95 * 95];               // 36.1 KB
    __shared__ __align__(16) __nv_bfloat16 ksm[64][40];       // 5.0 KB
    __shared__ __align__(16) __nv_bfloat16 vsm[64][40];       // 5.0 KB

    int b = blockIdx.z, h = blockIdx.y;
    int q0 = blockIdx.x * 64;
    int t = threadIdx.x;
    int w = t >> 5, lane = t & 31;
    int g = lane >> 2, tg = lane & 3;

    const float* bh = biasc + h * 9025;
    for (int i = t; i < 9025; i += 128) sb[i] = bh[i];

    const __nv_bfloat16* qb = q + ((size_t)(b * HEADS + h) * LL + q0 + w * 16) * HD;
    uint32_t qf[2][4];
    #pragma unroll
    for (int s2 = 0; s2 < 2; s2++) {
        int d0 = s2 * 16 + tg * 2;
        qf[s2][0] = *(const uint32_t*)(qb + (size_t)g       * HD + d0);
        qf[s2][1] = *(const uint32_t*)(qb + (size_t)(g + 8) * HD + d0);
        qf[s2][2] = *(const uint32_t*)(qb + (size_t)g       * HD + d0 + 8);
        qf[s2][3] = *(const uint32_t*)(qb + (size_t)(g + 8) * HD + d0 + 8);
    }

    int qi0 = q0 + w * 16 + g;
    int qi1 = qi0 + 8;
    int base0 = (qi0 / WW + 47) * 95 + (qi0 % WW) + 47;
    int base1 = (qi1 / WW + 47) * 95 + (qi1 % WW) + 47;

    float4 o[4];
    #pragma unroll
    for (int nt = 0; nt < 4; nt++) o[nt] = make_float4(0.f, 0.f, 0.f, 0.f);
    float mx0 = -1e30f, mx1 = -1e30f, ls0 = 0.f, ls1 = 0.f;

    const __nv_bfloat16* kb = k + (size_t)(b * HEADS + h) * LL * HD;
    const __nv_bfloat16* vb = v + (size_t)(b * HEADS + h) * LL * HD;

    for (int j0 = 0; j0 < LL; j0 += 64) {
        __syncthreads();
        // stage K and V tiles: 64 keys x 32 dims each (coalesced uint4)
        {
            int row = t >> 1, c0 = (t & 1) * 16;
            const uint4* ks_ = (const uint4*)(kb + (size_t)(j0 + row) * HD + c0);
            const uint4* vs_ = (const uint4*)(vb + (size_t)(j0 + row) * HD + c0);
            uint4 ku0 = ks_[0], ku1 = ks_[1];
            uint4 vu0 = vs_[0], vu1 = vs_[1];
            *(uint4*)&ksm[row][c0]     = ku0;
            *(uint4*)&ksm[row][c0 + 8] = ku1;
            *(uint4*)&vsm[row][c0]     = vu0;
            *(uint4*)&vsm[row][c0 + 8] = vu1;
        }
        __syncthreads();

        // ---- S = Q K^T (+bias), online max ----
        float s[8][4];
        float mt0 = -1e30f, mt1 = -1e30f;
        #pragma unroll
        for (int nt = 0; nt < 8; nt++) {
            int key = nt * 8 + g;
            uint32_t b00 = *(const uint32_t*)&ksm[key][tg * 2];
            uint32_t b01 = *(const uint32_t*)&ksm[key][tg * 2 + 8];
            uint32_t b10 = *(const uint32_t*)&ksm[key][tg * 2 + 16];
            uint32_t b11 = *(const uint32_t*)&ksm[key][tg * 2 + 24];
            float4 acc = make_float4(0.f, 0.f, 0.f, 0.f);
            mma_bf16(acc, qf[0], b00, b01);
            mma_bf16(acc, qf[1], b10, b11);

            int kj  = j0 + nt * 8 + tg * 2;
            int y0  = kj / WW,  x0 = kj - y0 * WW;
            int kj1 = kj + 1;
            int y1  = kj1 / WW, x1 = kj1 - y1 * WW;
            int c0i = y0 * 95 + x0, c1i = y1 * 95 + x1;

            float s0 = acc.x + sb[base0 - c0i];
            float s1 = acc.y + sb[base0 - c1i];
            float s2 = acc.z + sb[base1 - c0i];
            float s3 = acc.w + sb[base1 - c1i];
            s[nt][0] = s0; s[nt][1] = s1; s[nt][2] = s2; s[nt][3] = s3;
            mt0 = fmaxf(mt0, fmaxf(s0, s1));
            mt1 = fmaxf(mt1, fmaxf(s2, s3));
        }
        mt0 = fmaxf(mt0, __shfl_xor_sync(0xFFFFFFFFu, mt0, 1));
        mt0 = fmaxf(mt0, __shfl_xor_sync(0xFFFFFFFFu, mt0, 2));
        mt1 = fmaxf(mt1, __shfl_xor_sync(0xFFFFFFFFu, mt1, 1));
        mt1 = fmaxf(mt1, __shfl_xor_sync(0xFFFFFFFFu, mt1, 2));

        float nm0 = fmaxf(mx0, mt0), nm1 = fmaxf(mx1, mt1);
        float cr0 = __expf(mx0 - nm0), cr1 = __expf(mx1 - nm1);
        mx0 = nm0; mx1 = nm1;
        ls0 *= cr0; ls1 *= cr1;
        #pragma unroll
        for (int nt = 0; nt < 4; nt++) {
            o[nt].x *= cr0; o[nt].y *= cr0;
            o[nt].z *= cr1; o[nt].w *= cr1;
        }

        // ---- P = exp(S - m), packed into A fragments ----
        uint32_t pA[4][4];
        #pragma unroll
        for (int ks2 = 0; ks2 < 4; ks2++) {
            int ntA = 2 * ks2, ntB = 2 * ks2 + 1;
            float pa0 = __expf(s[ntA][0] - nm0), pa1 = __expf(s[ntA][1] - nm0);
            float pa2 = __expf(s[ntA][2] - nm1), pa3 = __expf(s[ntA][3] - nm1);
            float pb0 = __expf(s[ntB][0] - nm0), pb1 = __expf(s[ntB][1] - nm0);
            float pb2 = __expf(s[ntB][2] - nm1), pb3 = __expf(s[ntB][3] - nm1);
            ls0 += pa0 + pa1 + pb0 + pb1;
            ls1 += pa2 + pa3 + pb2 + pb3;
            pA[ks2][0] = packbf(pa0, pa1);
            pA[ks2][1] = packbf(pa2, pa3);
            pA[ks2][2] = packbf(pb0, pb1);
            pA[ks2][3] = packbf(pb2, pb3);
        }

        // ---- O += P V : V^T fragments via ldmatrix.trans ----
        #pragma unroll
        for (int ks2 = 0; ks2 < 4; ks2++) {
            int krow = ks2 * 16 + (lane & 15);
            int dcol = ((lane >> 4) & 1) * 8;
            uint32_t r0, r1, r2, r3;
            uint32_t a0 = (uint32_t)__cvta_generic_to_shared(&vsm[krow][dcol]);
            ldsm_x4_trans(r0, r1, r2, r3, a0);
            mma_bf16(o[0], pA[ks2], r0, r1);
            mma_bf16(o[1], pA[ks2], r2, r3);
            uint32_t a1 = (uint32_t)__cvta_generic_to_shared(&vsm[krow][dcol + 16]);
            ldsm_x4_trans(r0, r1, r2, r3, a1);
            mma_bf16(o[2], pA[ks2], r0, r1);
            mma_bf16(o[3], pA[ks2], r2, r3);
        }
    }

    // final row-sum reduce + normalize + bf16 store
    ls0 += __shfl_xor_sync(0xFFFFFFFFu, ls0, 1);
    ls0 += __shfl_xor_sync(0xFFFFFFFFu, ls0, 2);
    ls1 += __shfl_xor_sync(0xFFFFFFFFu, ls1, 1);
    ls1 += __shfl_xor_sync(0xFFFFFFFFu, ls1, 2);
    float i0 = 1.0f / ls0, i1 = 1.0f / ls1;

    __nv_bfloat16* o0p = ao + ((size_t)(b * LL) + qi0) * INNER + h * HD;
    __nv_bfloat16* o1p = ao + ((size_t)(b * LL) + qi1) * INNER + h * HD;
    #pragma unroll
    for (int nt = 0; nt < 4; nt++) {
        *(uint32_t*)&o0p[nt * 8 + tg * 2] = packbf(o[nt].x * i0, o[nt].y * i0);
        *(uint32_t*)&o1p[nt * 8 + tg * 2] = packbf(o[nt].z * i1, o[nt].w * i1);
    }
}

// ============================================================
extern "C" void kernel_launch(void* const* d_in, const int* in_sizes, int n_in,
                              void* d_out, int out_size) {
    const float* x    = (const float*)d_in[0];
    const float* ctx  = (const float*)d_in[1];
    const float* lnxw = (const float*)d_in[2];
    const float* lnxb = (const float*)d_in[3];
    const float* lncw = (const float*)d_in[4];
    const float* lncb = (const float*)d_in[5];
    const float* Wq   = (const float*)d_in[6];
    const float* bq   = (const float*)d_in[7];
    const float* Wk   = (const float*)d_in[8];
    const float* bk   = (const float*)d_in[9];
    const float* Wv   = (const float*)d_in[10];
    const float* bv   = (const float*)d_in[11];
    const float* Wp   = (const float*)d_in[12];
    const float* bp   = (const float*)d_in[13];
    const float* relt = (const float*)d_in[14];
    float* out = (float*)d_out;

    float *p_bias;
    __nv_bfloat16 *p_xnb, *p_cnb, *p_q, *p_k, *p_v, *p_ao;
    __nv_bfloat16 *p_wq, *p_wk, *p_wv, *p_wp;
    cudaGetSymbolAddress((void**)&p_xnb, g_xnb);
    cudaGetSymbolAddress((void**)&p_cnb, g_cnb);
    cudaGetSymbolAddress((void**)&p_q,  g_q);
    cudaGetSymbolAddress((void**)&p_k,  g_k);
    cudaGetSymbolAddress((void**)&p_v,  g_v);
    cudaGetSymbolAddress((void**)&p_ao, g_ao);
    cudaGetSymbolAddress((void**)&p_wq, g_wq);
    cudaGetSymbolAddress((void**)&p_wk, g_wk);
    cudaGetSymbolAddress((void**)&p_wv, g_wv);
    cudaGetSymbolAddress((void**)&p_wp, g_wp);
    cudaGetSymbolAddress((void**)&p_bias, g_bias);

    // 0) prep: weights -> bf16, compact bias table
    wconv_kernel<<<CH * INNER / 256, 256>>>(Wq, Wk, Wv, Wp, p_wq, p_wk, p_wv, p_wp);
    bias_prep_kernel<<<(HEADS * 95 * 95 + 255) / 256, 256>>>(relt, p_bias);

    // 1) layernorms -> bf16
    ln_kernel<<<BATCH * LL, 256>>>(x,   lnxw, lnxb, p_xnb);
    ln_kernel<<<BATCH * LL, 256>>>(ctx, lncw, lncb, p_cnb);

    // 2) Q/K/V projections (tensor core)
    dim3 gproj(BATCH * LL / 128, INNER / 64);
    gemm_mma<0><<<gproj, 256>>>(p_xnb, p_wq, bq, nullptr, p_q);
    gemm_mma<1><<<gproj, 256>>>(p_cnb, p_wk, bk, nullptr, p_k);
    gemm_mma<1><<<gproj, 256>>>(p_cnb, p_wv, bv, nullptr, p_v);

    // 3) tensor-core flash attention with relative bias
    dim3 gattn(LL / 64, HEADS, BATCH);
    attn_mma_kernel<<<gattn, 128>>>(p_q, p_k, p_v, p_bias, p_ao);

    // 4) output projection + residual (tensor core)
    dim3 gout(BATCH * LL / 128, CH / 64);
    gemm_mma<3><<<gout, 256>>>(p_ao, p_wp, bp, x, out);
}

// round 7
// speedup vs baseline: 6.1372x; 1.2464x over previous
#include <cuda_runtime.h>
#include <cuda_bf16.h>
#include <cuda_fp16.h>
#include <cstdint>
#include <stdint.h>

// ---------------- problem constants ----------------
#define BATCH 4
#define CH    256
#define HH    48
#define WW    48
#define LL    2304          // HH*WW
#define HEADS 8
#define HD    32
#define INNER 256           // HEADS*HD
#define SCALE 0.17677669529663687f   // 1/sqrt(32)
#define LOG2E 1.4426950408889634f

// ---------------- scratch (static device allocations; no cudaMalloc) ------
__device__ __align__(16) __nv_bfloat16 g_xnb[BATCH * LL * CH];         // ln(x)   [b][l][c]
__device__ __align__(16) __nv_bfloat16 g_cnb[BATCH * LL * CH];         // ln(ctx) [b][l][c]
__device__ __align__(16) __nv_bfloat16 g_q [BATCH * HEADS * LL * HD];  // [b][h][l][d] (scaled by SCALE*LOG2E)
__device__ __align__(16) __nv_bfloat16 g_k [BATCH * HEADS * LL * HD];  // [b][h][l][d]
__device__ __align__(16) __half        g_v [BATCH * HEADS * LL * HD];  // [b][h][l][d] f16
__device__ __align__(16) __nv_bfloat16 g_ao[BATCH * LL * INNER];       // attention out bf16
__device__ __align__(16) __nv_bfloat16 g_wq[CH * INNER];
__device__ __align__(16) __nv_bfloat16 g_wk[CH * INNER];
__device__ __align__(16) __nv_bfloat16 g_wv[CH * INNER];
__device__ __align__(16) __nv_bfloat16 g_wp[CH * INNER];
__device__ float g_bias[HEADS * 95 * 95];      // compact per-head bias, pre-multiplied by LOG2E

// ---------------- helpers ----------------
__device__ __forceinline__ uint32_t packbf(float lo, float hi) {
    __nv_bfloat162 p = __floats2bfloat162_rn(lo, hi);
    return *(uint32_t*)&p;
}
__device__ __forceinline__ uint32_t packh(float lo, float hi) {
    __half2 p = __floats2half2_rn(lo, hi);
    return *(uint32_t*)&p;
}
// 2^a, 2^b in f16, packed (single MUFU op)
__device__ __forceinline__ uint32_t exp2_h2(float a, float b) {
    __half2 d = __floats2half2_rn(a, b);
    uint32_t din = *(uint32_t*)&d, r;
    asm("ex2.approx.f16x2 %0, %1;\n" : "=r"(r) : "r"(din));
    return r;
}

__device__ __forceinline__ void mma_bf16(float4& c, const uint32_t a[4],
                                         uint32_t b0, uint32_t b1) {
    asm volatile(
        "mma.sync.aligned.m16n8k16.row.col.f32.bf16.bf16.f32 "
        "{%0,%1,%2,%3}, {%4,%5,%6,%7}, {%8,%9}, {%0,%1,%2,%3};\n"
        : "+f"(c.x), "+f"(c.y), "+f"(c.z), "+f"(c.w)
        : "r"(a[0]), "r"(a[1]), "r"(a[2]), "r"(a[3]), "r"(b0), "r"(b1));
}
__device__ __forceinline__ void mma_f16(float4& c, const uint32_t a[4],
                                        uint32_t b0, uint32_t b1) {
    asm volatile(
        "mma.sync.aligned.m16n8k16.row.col.f32.f16.f16.f32 "
        "{%0,%1,%2,%3}, {%4,%5,%6,%7}, {%8,%9}, {%0,%1,%2,%3};\n"
        : "+f"(c.x), "+f"(c.y), "+f"(c.z), "+f"(c.w)
        : "r"(a[0]), "r"(a[1]), "r"(a[2]), "r"(a[3]), "r"(b0), "r"(b1));
}
__device__ __forceinline__ void ldsm_x4_trans(uint32_t& r0, uint32_t& r1,
                                              uint32_t& r2, uint32_t& r3,
                                              uint32_t saddr) {
    asm volatile(
        "ldmatrix.sync.aligned.m8n8.x4.trans.shared.b16 {%0,%1,%2,%3}, [%4];\n"
        : "=r"(r0), "=r"(r1), "=r"(r2), "=r"(r3) : "r"(saddr));
}

// ============================================================
// Weight fp32 -> bf16 conversion
// ============================================================
__global__ void wconv_kernel(const float* __restrict__ a, const float* __restrict__ b,
                             const float* __restrict__ c, const float* __restrict__ d,
                             __nv_bfloat16* __restrict__ oa, __nv_bfloat16* __restrict__ ob,
                             __nv_bfloat16* __restrict__ oc, __nv_bfloat16* __restrict__ od) {
    int i = blockIdx.x * 256 + threadIdx.x;
    oa[i] = __float2bfloat16(a[i]);
    ob[i] = __float2bfloat16(b[i]);
    oc[i] = __float2bfloat16(c[i]);
    od[i] = __float2bfloat16(d[i]);
}

// ============================================================
// Bias precompute: g_bias[h][dy+47][dx+47] * LOG2E
// ============================================================
__global__ void bias_prep_kernel(const float* __restrict__ rel_table,
                                 float* __restrict__ out) {
    int i = blockIdx.x * 256 + threadIdx.x;
    if (i < HEADS * 95 * 95) {
        int h = i / (95 * 95), r = i % (95 * 95);
        int dy = r / 95, dx = r % 95;
        out[i] = rel_table[((dy + 16) * 127 + (dx + 16)) * HEADS + h] * LOG2E;
    }
}

// ============================================================
// LayerNorm, coalesced tile version.
// Block = 32 positions x 256 channels. Phase 1: coalesced fp32 loads
// (warp spans 32 consecutive l), cache tile in smem, reduce over c.
// Phase 2: bf16 [l][c] rows written coalesced as uint32.
// ============================================================
__global__ void __launch_bounds__(256) ln_kernel(
        const float* __restrict__ src,
        const float* __restrict__ w,
        const float* __restrict__ bia,
        __nv_bfloat16* __restrict__ dst) {
    __shared__ float tile[256][33];   // [c][l], pad 33
    __shared__ float red1[8][32], red2[8][32];
    __shared__ float smu[32], sinv[32];

    int blk = blockIdx.x;                   // 0..BATCH*72-1
    int b = blk / (LL / 32), lt = blk % (LL / 32);
    int l0 = lt * 32;
    int t = threadIdx.x;
    int lsub = t & 31, cb = t >> 5;         // warp w loads channel rows cb==w

    const float* sp = src + (size_t)b * CH * LL + l0 + lsub;
    float sa = 0.f, sq = 0.f;
    #pragma unroll
    for (int i = 0; i < 32; i++) {
        int c = cb + i * 8;
        float v = sp[(size_t)c * LL];       // coalesced: 32 consecutive l per warp
        tile[c][lsub] = v;
        sa += v; sq += v * v;
    }
    red1[cb][lsub] = sa; red2[cb][lsub] = sq;
    __syncthreads();
    if (t < 32) {
        float suma = 0.f, sumq = 0.f;
        #pragma unroll
        for (int j = 0; j < 8; j++) { suma += red1[j][t]; sumq += red2[j][t]; }
        float mu  = suma * (1.0f / 256.0f);
        float var = sumq * (1.0f / 256.0f) - mu * mu;
        smu[t] = mu; sinv[t] = rsqrtf(var + 1e-6f);
    }
    __syncthreads();

    __nv_bfloat16* dp = dst + (size_t)(b * LL + l0) * CH;
    #pragma unroll
    for (int i = 0; i < 16; i++) {
        int idx = t + i * 256;              // 4096 u32 = 32 rows x 128 u32
        int l = idx >> 7, cp = (idx & 127) * 2;
        float mu = smu[l], inv = sinv[l];
        float v0 = (tile[cp    ][l] - mu) * inv * w[cp    ] + bia[cp    ];
        float v1 = (tile[cp + 1][l] - mu) * inv * w[cp + 1] + bia[cp + 1];
        *(uint32_t*)&dp[(size_t)l * CH + cp] = packbf(v0, v1);
    }
}

// ============================================================
// Tensor-core GEMM: C[M=9216][N] = A[M][256] * W[N][256]^T (+bias)
// MODE 0: Q epilogue (scale by SCALE*LOG2E, bf16 out [b][h][l][d])
// MODE 1: K epilogue (bf16 out [b][h][l][d])
// MODE 2: V epilogue (f16  out [b][h][l][d])
// MODE 3: out-proj epilogue (fp32 out [b][c][l] + residual via smem transpose)
// ============================================================
template<int MODE>
__global__ void __launch_bounds__(256) gemm_mma(
    const __nv_bfloat16* __restrict__ A,
    const __nv_bfloat16* __restrict__ W,
    const float* __restrict__ bias,
    const float* __restrict__ xres,
    void* __restrict__ outp) {
    constexpr int SMB = (MODE == 3) ? 34048 : 27648;
    __shared__ __align__(16) char smraw[SMB];
    __nv_bfloat16 (*As)[72] = (__nv_bfloat16(*)[72])smraw;
    __nv_bfloat16 (*Ws)[72] = (__nv_bfloat16(*)[72])(smraw + 128 * 72 * 2);

    int m0 = blockIdx.x * 128, n0 = blockIdx.y * 64;
    int tid = threadIdx.x;
    int w = tid >> 5, lane = tid & 31, g = lane >> 2, tg = lane & 3;
    int wm = (w & 3) * 32, wn = (w >> 2) * 32;

    float4 acc[2][4];
    #pragma unroll
    for (int mf = 0; mf < 2; mf++)
        #pragma unroll
        for (int nf = 0; nf < 4; nf++) acc[mf][nf] = make_float4(0.f, 0.f, 0.f, 0.f);

    for (int k0 = 0; k0 < 256; k0 += 64) {
        __syncthreads();
        #pragma unroll
        for (int i = 0; i < 4; i++) {
            int idx = tid + i * 256;
            int r = idx >> 3, c8 = (idx & 7) * 8;
            *(uint4*)&As[r][c8] = *(const uint4*)&A[(size_t)(m0 + r) * 256 + k0 + c8];
        }
        #pragma unroll
        for (int i = 0; i < 2; i++) {
            int idx = tid + i * 256;
            int r = idx >> 3, c8 = (idx & 7) * 8;
            *(uint4*)&Ws[r][c8] = *(const uint4*)&W[(size_t)(n0 + r) * 256 + k0 + c8];
        }
        __syncthreads();

        #pragma unroll
        for (int kk = 0; kk < 4; kk++) {
            uint32_t af[2][4];
            #pragma unroll
            for (int mf = 0; mf < 2; mf++) {
                int r = wm + mf * 16 + g;
                af[mf][0] = *(const uint32_t*)&As[r    ][kk * 16 + tg * 2];
                af[mf][1] = *(const uint32_t*)&As[r + 8][kk * 16 + tg * 2];
                af[mf][2] = *(const uint32_t*)&As[r    ][kk * 16 + tg * 2 + 8];
                af[mf][3] = *(const uint32_t*)&As[r + 8][kk * 16 + tg * 2 + 8];
            }
            #pragma unroll
            for (int nf = 0; nf < 4; nf++) {
                int rn = wn + nf * 8 + g;
                uint32_t b0 = *(const uint32_t*)&Ws[rn][kk * 16 + tg * 2];
                uint32_t b1 = *(const uint32_t*)&Ws[rn][kk * 16 + tg * 2 + 8];
                mma_bf16(acc[0][nf], af[0], b0, b1);
                mma_bf16(acc[1][nf], af[1], b0, b1);
            }
        }
    }

    if (MODE != 3) {
        const float sc = (MODE == 0) ? (SCALE * LOG2E) : 1.0f;
        __nv_bfloat16* out = (__nv_bfloat16*)outp;   // addressing valid for half too
        #pragma unroll
        for (int mf = 0; mf < 2; mf++) {
            int m = m0 + wm + mf * 16 + g;
            int bb = m / LL, l = m % LL;
            #pragma unroll
            for (int nf = 0; nf < 4; nf++) {
                int col = n0 + wn + nf * 8 + tg * 2;
                int h = col >> 5, d = col & 31;
                float bs0 = bias[col], bs1 = bias[col + 1];
                float4 c = acc[mf][nf];
                uint32_t lo, hi;
                if (MODE == 2) {
                    lo = packh(c.x + bs0, c.y + bs1);
                    hi = packh(c.z + bs0, c.w + bs1);
                } else {
                    lo = packbf((c.x + bs0) * sc, (c.y + bs1) * sc);
                    hi = packbf((c.z + bs0) * sc, (c.w + bs1) * sc);
                }
                size_t base = (size_t)(bb * HEADS + h) * LL;
                *(uint32_t*)&out[(base + l    ) * HD + d] = lo;
                *(uint32_t*)&out[(base + l + 8) * HD + d] = hi;
            }
        }
    } else {
        float (*Ct)[132] = (float(*)[132])smraw;
        __syncthreads();
        #pragma unroll
        for (int mf = 0; mf < 2; mf++) {
            int ml = wm + mf * 16 + g;
            #pragma unroll
            for (int nf = 0; nf < 4; nf++) {
                int cn = wn + nf * 8 + tg * 2;
                float4 c = acc[mf][nf];
                Ct[cn    ][ml    ] = c.x;
                Ct[cn + 1][ml    ] = c.y;
                Ct[cn    ][ml + 8] = c.z;
                Ct[cn + 1][ml + 8] = c.w;
            }
        }
        __syncthreads();
        float* out = (float*)outp;
        int b_ = m0 / LL, l0 = m0 % LL;
        #pragma unroll
        for (int i = 0; i < 8; i++) {
            int idx = tid + i * 256;
            int cr = idx >> 5, l4 = (idx & 31) * 4;
            int col = n0 + cr;
            size_t gaddr = (size_t)(b_ * CH + col) * LL + l0 + l4;
            float4 rx = *(const float4*)&xres[gaddr];
            float bb = bias[col];
            float4 r;
            r.x = Ct[cr][l4 + 0] + bb + rx.x;
            r.y = Ct[cr][l4 + 1] + bb + rx.y;
            r.z = Ct[cr][l4 + 2] + bb + rx.z;
            r.w = Ct[cr][l4 + 3] + bb + rx.w;
            *(float4*)&out[gaddr] = r;
        }
    }
}

// ============================================================
// Flash attention, log2-domain softmax + f16x2 exp + f16 PV mma.
// 4 warps / block, 16 queries per warp, 64-key tiles.
// ============================================================
__global__ void __launch_bounds__(128)
attn_mma_kernel(const __nv_bfloat16* __restrict__ q,
                const __nv_bfloat16* __restrict__ k,
                const __half* __restrict__ v,
                const float* __restrict__ biasc,
                __nv_bfloat16* __restrict__ ao) {
    __shared__ __align__(16) float sb[95 * 95];               // 36.1 KB
    __shared__ __align__(16) __nv_bfloat16 ksm[64][40];       // 5.0 KB
    __shared__ __align__(16) __half        vsm[64][40];       // 5.0 KB

    int b = blockIdx.z, h = blockIdx.y;
    int q0 = blockIdx.x * 64;
    int t = threadIdx.x;
    int w = t >> 5, lane = t & 31;
    int g = lane >> 2, tg = lane & 3;

    const float* bh = biasc + h * 9025;
    for (int i = t; i < 9025; i += 128) sb[i] = bh[i];

    const __nv_bfloat16* qb = q + ((size_t)(b * HEADS + h) * LL + q0 + w * 16) * HD;
    uint32_t qf[2][4];
    #pragma unroll
    for (int s2 = 0; s2 < 2; s2++) {
        int d0 = s2 * 16 + tg * 2;
        qf[s2][0] = *(const uint32_t*)(qb + (size_t)g       * HD + d0);
        qf[s2][1] = *(const uint32_t*)(qb + (size_t)(g + 8) * HD + d0);
        qf[s2][2] = *(const uint32_t*)(qb + (size_t)g       * HD + d0 + 8);
        qf[s2][3] = *(const uint32_t*)(qb + (size_t)(g + 8) * HD + d0 + 8);
    }

    int qi0 = q0 + w * 16 + g;
    int qi1 = qi0 + 8;
    int base0 = (qi0 / WW + 47) * 95 + (qi0 % WW) + 47;
    int base1 = (qi1 / WW + 47) * 95 + (qi1 % WW) + 47;

    float4 o[4];
    #pragma unroll
    for (int nt = 0; nt < 4; nt++) o[nt] = make_float4(0.f, 0.f, 0.f, 0.f);
    float mx0 = -1e30f, mx1 = -1e30f, ls0 = 0.f, ls1 = 0.f;

    const __nv_bfloat16* kb = k + (size_t)(b * HEADS + h) * LL * HD;
    const __half*        vb = v + (size_t)(b * HEADS + h) * LL * HD;

    for (int j0 = 0; j0 < LL; j0 += 64) {
        __syncthreads();
        {
            int row = t >> 1, c0 = (t & 1) * 16;
            const uint4* ks_ = (const uint4*)(kb + (size_t)(j0 + row) * HD + c0);
            const uint4* vs_ = (const uint4*)(vb + (size_t)(j0 + row) * HD + c0);
            uint4 ku0 = ks_[0], ku1 = ks_[1];
            uint4 vu0 = vs_[0], vu1 = vs_[1];
            *(uint4*)&ksm[row][c0]     = ku0;
            *(uint4*)&ksm[row][c0 + 8] = ku1;
            *(uint4*)&vsm[row][c0]     = vu0;
            *(uint4*)&vsm[row][c0 + 8] = vu1;
        }
        __syncthreads();

        // ---- S = Q K^T (+bias), log2 domain, online max ----
        float s[8][4];
        float mt0 = -1e30f, mt1 = -1e30f;
        #pragma unroll
        for (int nt = 0; nt < 8; nt++) {
            int key = nt * 8 + g;
            uint32_t b00 = *(const uint32_t*)&ksm[key][tg * 2];
            uint32_t b01 = *(const uint32_t*)&ksm[key][tg * 2 + 8];
            uint32_t b10 = *(const uint32_t*)&ksm[key][tg * 2 + 16];
            uint32_t b11 = *(const uint32_t*)&ksm[key][tg * 2 + 24];
            float4 acc = make_float4(0.f, 0.f, 0.f, 0.f);
            mma_bf16(acc, qf[0], b00, b01);
            mma_bf16(acc, qf[1], b10, b11);

            int kj  = j0 + nt * 8 + tg * 2;
            int y0  = kj / WW,  x0 = kj - y0 * WW;
            int kj1 = kj + 1;
            int y1  = kj1 / WW, x1 = kj1 - y1 * WW;
            int c0i = y0 * 95 + x0, c1i = y1 * 95 + x1;

            float s0 = acc.x + sb[base0 - c0i];
            float s1 = acc.y + sb[base0 - c1i];
            float s2 = acc.z + sb[base1 - c0i];
            float s3 = acc.w + sb[base1 - c1i];
            s[nt][0] = s0; s[nt][1] = s1; s[nt][2] = s2; s[nt][3] = s3;
            mt0 = fmaxf(mt0, fmaxf(s0, s1));
            mt1 = fmaxf(mt1, fmaxf(s2, s3));
        }
        mt0 = fmaxf(mt0, __shfl_xor_sync(0xFFFFFFFFu, mt0, 1));
        mt0 = fmaxf(mt0, __shfl_xor_sync(0xFFFFFFFFu, mt0, 2));
        mt1 = fmaxf(mt1, __shfl_xor_sync(0xFFFFFFFFu, mt1, 1));
        mt1 = fmaxf(mt1, __shfl_xor_sync(0xFFFFFFFFu, mt1, 2));

        float nm0 = fmaxf(mx0, mt0), nm1 = fmaxf(mx1, mt1);
        float cr0 = exp2f(mx0 - nm0), cr1 = exp2f(mx1 - nm1);
        mx0 = nm0; mx1 = nm1;
        ls0 *= cr0; ls1 *= cr1;
        #pragma unroll
        for (int nt = 0; nt < 4; nt++) {
            o[nt].x *= cr0; o[nt].y *= cr0;
            o[nt].z *= cr1; o[nt].w *= cr1;
        }

        // ---- P = 2^(S-m) in f16x2, packed directly as f16 A fragments ----
        uint32_t pA[4][4];
        __half2 hs0 = __float2half2_rn(0.f), hs1 = __float2half2_rn(0.f);
        #pragma unroll
        for (int ks2 = 0; ks2 < 4; ks2++) {
            int ntA = 2 * ks2, ntB = 2 * ks2 + 1;
            pA[ks2][0] = exp2_h2(s[ntA][0] - nm0, s[ntA][1] - nm0);
            pA[ks2][1] = exp2_h2(s[ntA][2] - nm1, s[ntA][3] - nm1);
            pA[ks2][2] = exp2_h2(s[ntB][0] - nm0, s[ntB][1] - nm0);
            pA[ks2][3] = exp2_h2(s[ntB][2] - nm1, s[ntB][3] - nm1);
            hs0 = __hadd2(hs0, __hadd2(*(__half2*)&pA[ks2][0], *(__half2*)&pA[ks2][2]));
            hs1 = __hadd2(hs1, __hadd2(*(__half2*)&pA[ks2][1], *(__half2*)&pA[ks2][3]));
        }
        float2 f0 = __half22float2(hs0), f1 = __half22float2(hs1);
        ls0 += f0.x + f0.y;
        ls1 += f1.x + f1.y;

        // ---- O += P V (f16 mma), V^T fragments via ldmatrix.trans ----
        #pragma unroll
        for (int ks2 = 0; ks2 < 4; ks2++) {
            int krow = ks2 * 16 + (lane & 15);
            int dcol = ((lane >> 4) & 1) * 8;
            uint32_t r0, r1, r2, r3;
            uint32_t a0 = (uint32_t)__cvta_generic_to_shared(&vsm[krow][dcol]);
            ldsm_x4_trans(r0, r1, r2, r3, a0);
            mma_f16(o[0], pA[ks2], r0, r1);
            mma_f16(o[1], pA[ks2], r2, r3);
            uint32_t a1 = (uint32_t)__cvta_generic_to_shared(&vsm[krow][dcol + 16]);
            ldsm_x4_trans(r0, r1, r2, r3, a1);
            mma_f16(o[2], pA[ks2], r0, r1);
            mma_f16(o[3], pA[ks2], r2, r3);
        }
    }

    ls0 += __shfl_xor_sync(0xFFFFFFFFu, ls0, 1);
    ls0 += __shfl_xor_sync(0xFFFFFFFFu, ls0, 2);
    ls1 += __shfl_xor_sync(0xFFFFFFFFu, ls1, 1);
    ls1 += __shfl_xor_sync(0xFFFFFFFFu, ls1, 2);
    float i0 = 1.0f / ls0, i1 = 1.0f / ls1;

    __nv_bfloat16* o0p = ao + ((size_t)(b * LL) + qi0) * INNER + h * HD;
    __nv_bfloat16* o1p = ao + ((size_t)(b * LL) + qi1) * INNER + h * HD;
    #pragma unroll
    for (int nt = 0; nt < 4; nt++) {
        *(uint32_t*)&o0p[nt * 8 + tg * 2] = packbf(o[nt].x * i0, o[nt].y * i0);
        *(uint32_t*)&o1p[nt * 8 + tg * 2] = packbf(o[nt].z * i1, o[nt].w * i1);
    }
}

// ============================================================
extern "C" void kernel_launch(void* const* d_in, const int* in_sizes, int n_in,
                              void* d_out, int out_size) {
    const float* x    = (const float*)d_in[0];
    const float* ctx  = (const float*)d_in[1];
    const float* lnxw = (const float*)d_in[2];
    const float* lnxb = (const float*)d_in[3];
    const float* lncw = (const float*)d_in[4];
    const float* lncb = (const float*)d_in[5];
    const float* Wq   = (const float*)d_in[6];
    const float* bq   = (const float*)d_in[7];
    const float* Wk   = (const float*)d_in[8];
    const float* bk   = (const float*)d_in[9];
    const float* Wv   = (const float*)d_in[10];
    const float* bv   = (const float*)d_in[11];
    const float* Wp   = (const float*)d_in[12];
    const float* bp   = (const float*)d_in[13];
    const float* relt = (const float*)d_in[14];
    float* out = (float*)d_out;

    float *p_bias;
    __nv_bfloat16 *p_xnb, *p_cnb, *p_q, *p_k, *p_ao;
    __half *p_v;
    __nv_bfloat16 *p_wq, *p_wk, *p_wv, *p_wp;
    cudaGetSymbolAddress((void**)&p_xnb, g_xnb);
    cudaGetSymbolAddress((void**)&p_cnb, g_cnb);
    cudaGetSymbolAddress((void**)&p_q,  g_q);
    cudaGetSymbolAddress((void**)&p_k,  g_k);
    cudaGetSymbolAddress((void**)&p_v,  g_v);
    cudaGetSymbolAddress((void**)&p_ao, g_ao);
    cudaGetSymbolAddress((void**)&p_wq, g_wq);
    cudaGetSymbolAddress((void**)&p_wk, g_wk);
    cudaGetSymbolAddress((void**)&p_wv, g_wv);
    cudaGetSymbolAddress((void**)&p_wp, g_wp);
    cudaGetSymbolAddress((void**)&p_bias, g_bias);

    // 0) prep: weights -> bf16, compact bias table (log2 domain)
    wconv_kernel<<<CH * INNER / 256, 256>>>(Wq, Wk, Wv, Wp, p_wq, p_wk, p_wv, p_wp);
    bias_prep_kernel<<<(HEADS * 95 * 95 + 255) / 256, 256>>>(relt, p_bias);

    // 1) layernorms -> bf16 (coalesced tile version)
    ln_kernel<<<BATCH * (LL / 32), 256>>>(x,   lnxw, lnxb, p_xnb);
    ln_kernel<<<BATCH * (LL / 32), 256>>>(ctx, lncw, lncb, p_cnb);

    // 2) Q/K/V projections (tensor core)
    dim3 gproj(BATCH * LL / 128, INNER / 64);
    gemm_mma<0><<<gproj, 256>>>(p_xnb, p_wq, bq, nullptr, p_q);
    gemm_mma<1><<<gproj, 256>>>(p_cnb, p_wk, bk, nullptr, p_k);
    gemm_mma<2><<<gproj, 256>>>(p_cnb, p_wv, bv, nullptr, p_v);

    // 3) tensor-core flash attention with relative bias
    dim3 gattn(LL / 64, HEADS, BATCH);
    attn_mma_kernel<<<gattn, 128>>>(p_q, p_k, p_v, p_bias, p_ao);

    // 4) output projection + residual (tensor core)
    dim3 gout(BATCH * LL / 128, CH / 64);
    gemm_mma<3><<<gout, 256>>>(p_ao, p_wp, bp, x, out);
}